// round 16
// baseline (speedup 1.0000x reference)
#include <cuda_runtime.h>
#include <cstdint>

// SlidingWindowCmn (16, 60000, 80) fp32, window=600, min=100, center=False,
// norm_vars=True.
// R6 architecture with WARP-DECOUPLED fills: thread f cp.asyncs feature
// block 4*(f/4)..+3 for rows f%4+{0,4,8,12} of each 16-row group, so every
// feature column is written by threads of its own warp. The per-group CTA
// __syncthreads becomes __syncwarp (bar.warp.sync gives the memory ordering
// after each thread's cp.async.wait_group), letting the 3 warps run as
// independent pipelines. Ring 704 rows (+8 mirror), lead = 5 groups,
// issue-after-consume overwrite safety per R6 proof (now per-warp).

namespace {
constexpr int kB      = 16;
constexpr int kT      = 60000;
constexpr int kF      = 80;
constexpr int kWin    = 600;
constexpr int kMin    = 100;
constexpr int kChunks = 9;
constexpr int kL      = 6672;               // 8*6672 + 6624 = 60000
constexpr int kRL     = 704;                // logical ring rows
constexpr int kRLf    = kRL * kF;           // 56320 floats
constexpr uint32_t kRLb = kRL * 320u;       // 225280 bytes (logical)
constexpr uint32_t kSmemB = (kRL + 8) * 320u;   // 227840 bytes (+8 mirror)
constexpr int kVOf    = (kRL - kWin - 1) * kF;  // 103 rows -> 8240 floats
constexpr float kInvW = 1.0f / 601.0f;
constexpr int kGrid   = kB * kChunks;       // 144
}

__device__ __forceinline__ uint32_t smem_u32(const void* p) {
    uint32_t a;
    asm("{ .reg .u64 t; cvta.to.shared.u64 t, %1; cvt.u32.u64 %0, t; }"
        : "=r"(a) : "l"(p));
    return a;
}
__device__ __forceinline__ void cpa16(uint32_t s, const float* g) {
    asm volatile("cp.async.cg.shared.global [%0], [%1], 16;" :: "r"(s), "l"(g));
}
__device__ __forceinline__ void cpcommit() {
    asm volatile("cp.async.commit_group;" ::: "memory");
}
__device__ __forceinline__ void cpwait4() {
    asm volatile("cp.async.wait_group 4;" ::: "memory");
}

__global__ void __launch_bounds__(kF, 1)
cmn_kernel(const float* __restrict__ x, float* __restrict__ out)
{
    extern __shared__ float ring[];
    const int f = threadIdx.x;                    // feature 0..79
    const int c = blockIdx.x % kChunks;
    const int b = blockIdx.x / kChunks;

    // warp-local sync mask (warp 2 has 16 live lanes)
    const unsigned wmask = (f < 64) ? 0xffffffffu : 0x0000ffffu;

    const float* xb = x + (size_t)b * kT * kF;
    const int start = c * kL;
    const int end   = (c == kChunks - 1) ? kT : start + kL;

    const uint32_t rsb = smem_u32(ring);
    const float* pClamp = x + ((size_t)kB * kT - 16) * kF;  // last full group

    // warp-self-contained fill mapping
    const int fb = (f >> 2) << 2;                 // feature block base (4f/4)
    const int rp = f & 3;                         // row phase 0..3
    const int thrOffG = rp * kF + fb;             // global float offset
    const uint32_t thrOffS = (uint32_t)(rp * 320 + fb * 4);  // smem bytes

    int vnF;                  // consume group float-offset (slot*80)
    uint32_t issB;            // issue group byte-offset
    const float* pIss;
    if (c == 0) {
        vnF = 0; issB = 0; pIss = xb;
    } else {
        const int t0   = start - 608;             // 16-aligned; 7 pad + 601 warmup
        const int slot = t0 % kRL;                // multiple of 16
        vnF = slot * kF; issB = (uint32_t)slot * 320u;
        pIss = xb + (size_t)t0 * kF;
    }

    auto issue16 = [&]() {
        const float* q  = (pIss > pClamp) ? pClamp : pIss;
        const float* qt = q + thrOffG;            // rows rp, rp+4, rp+8, rp+12
        const uint32_t a = rsb + issB + thrOffS;
        cpa16(a,         qt);
        cpa16(a + 1280u, qt + 320);
        cpa16(a + 2560u, qt + 640);
        cpa16(a + 3840u, qt + 960);
        if (issB == 0) {                          // wrap group: mirror rows 0..7
            const uint32_t m = rsb + kRLb + thrOffS;
            cpa16(m,         qt);                 // row rp
            cpa16(m + 1280u, qt + 320);           // row rp+4
        }
        cpcommit();
        pIss += 16 * kF;
        issB += 5120u; if (issB == kRLb) issB = 0;
    };

    // prologue: 5 groups (80 rows) in flight
    #pragma unroll 1
    for (int g = 0; g < 5; ++g) issue16();

    float s = 0.f, ss = 0.f, mean = 0.f, qss = 0.f;
    float* po = out + (size_t)b * kT * kF + f;
    int nSteady;

    if (c == 0) {
        // groups 0..5: rows 0..95 accumulate
        #pragma unroll 1
        for (int g = 0; g < 6; ++g) {
            cpwait4(); __syncwarp(wmask);
            const float* rv = ring + vnF + f;
            #pragma unroll
            for (int u = 0; u < 16; ++u) {
                float v = rv[u * kF]; s += v; ss = __fmaf_rn(v, v, ss);
            }
            vnF += 16 * kF; issue16();
        }
        // group 6: rows 96..111
        {
            cpwait4(); __syncwarp(wmask);
            const float* rv = ring + vnF + f;
            #pragma unroll
            for (int u = 0; u < 4; ++u) {          // rows 96..99
                float v = rv[u * kF]; s += v; ss = __fmaf_rn(v, v, ss);
            }
            const float inv = 1.0f / (float)kMin;  // burst rows 0..99
            const float m0  = s * inv;
            const float vr0 = __fmaf_rn(-m0, m0, ss * inv);
            const float rs0 = rsqrtf(vr0);
            #pragma unroll 4
            for (int t = 0; t < kMin; ++t) {
                float v = ring[t * kF + f];
                __stcs(po + t * kF, (v - m0) * rs0);
            }
            float n = 100.0f;
            #pragma unroll
            for (int u = 4; u < 16; ++u) {         // rows 100..111 growing
                float v = rv[u * kF]; s += v; ss = __fmaf_rn(v, v, ss);
                n += 1.0f;
                float inv2 = __fdividef(1.0f, n);
                float m    = s * inv2;
                float var  = __fmaf_rn(-m, m, ss * inv2);
                __stcs(po + (96 + u) * kF, (v - m) * rsqrtf(var));
            }
            vnF += 16 * kF; issue16();
        }
        // groups 7..36: rows 112..591 growing
        po += 112 * kF;
        float n = 112.0f;
        #pragma unroll 1
        for (int g = 7; g < 37; ++g) {
            cpwait4(); __syncwarp(wmask);
            const float* rv = ring + vnF + f;
            #pragma unroll
            for (int u = 0; u < 16; ++u) {
                float v = rv[u * kF]; s += v; ss = __fmaf_rn(v, v, ss);
                n += 1.0f;
                float inv = __fdividef(1.0f, n);
                float m   = s * inv;
                float var = __fmaf_rn(-m, m, ss * inv);
                __stcs(po + u * kF, (v - m) * rsqrtf(var));
            }
            vnF += 16 * kF; po += 16 * kF; issue16();
        }
        // group 37: rows 592..607 (transition at t=600)
        {
            cpwait4(); __syncwarp(wmask);
            const float* rv = ring + vnF + f;
            #pragma unroll
            for (int u = 0; u < 8; ++u) {          // rows 592..599 growing
                float v = rv[u * kF]; s += v; ss = __fmaf_rn(v, v, ss);
                n += 1.0f;
                float inv = __fdividef(1.0f, n);
                float m   = s * inv;
                float var = __fmaf_rn(-m, m, ss * inv);
                __stcs(po + u * kF, (v - m) * rsqrtf(var));
            }
            mean = s * kInvW; qss = ss * kInvW;
            #pragma unroll
            for (int u = 8; u < 16; ++u) {         // rows 600..607 steady-1
                float vn = rv[u * kF];
                float vo = (u == 8) ? 0.0f : ring[(u - 9) * kF + f];
                float t1 = (vn - vo) * kInvW;
                mean += t1;
                qss   = __fmaf_rn(t1, vn + vo, qss);
                float var = __fmaf_rn(-mean, mean, qss);
                __stcs(po + u * kF, (vn - mean) * rsqrtf(var));
            }
            vnF += 16 * kF; issue16();             // vnF = 608*kF
        }
        nSteady = (kL - 608) / 16;                 // 379
    } else {
        // warmup group 0: rows t0+7 .. t0+15 (start-601 .. start-593)
        {
            cpwait4(); __syncwarp(wmask);
            const float* rv = ring + vnF + f;
            #pragma unroll
            for (int u = 7; u < 16; ++u) {
                float v = rv[u * kF]; s += v; ss = __fmaf_rn(v, v, ss);
            }
            vnF += 16 * kF; if (vnF == kRLf) vnF = 0;
            issue16();
        }
        // warmup groups 1..37: 592 rows
        #pragma unroll 1
        for (int g = 1; g < 38; ++g) {
            cpwait4(); __syncwarp(wmask);
            const float* rv = ring + vnF + f;
            #pragma unroll
            for (int u = 0; u < 16; ++u) {
                float v = rv[u * kF]; s += v; ss = __fmaf_rn(v, v, ss);
            }
            vnF += 16 * kF; if (vnF == kRLf) vnF = 0;
            issue16();
        }
        mean = s * kInvW; qss = ss * kInvW;
        nSteady = (end - start) / 16;              // 417 or 414
    }

    // ---- steady sliding loop ----
    const int g0row = (c == 0) ? 608 : start;
    float* po2 = out + (size_t)b * kT * kF + (size_t)g0row * kF + f;
    #pragma unroll 1
    for (int g = 0; g < nSteady; ++g) {
        cpwait4(); __syncwarp(wmask);
        const float* rvn = ring + vnF + f;
        int voF = vnF + kVOf;                      // slot (t-601), group-aligned
        if (voF >= kRLf) voF -= kRLf;              // one wrap check / 16 rows
        const float* rvo = ring + voF + f;         // mirror covers straddle
        #pragma unroll
        for (int u = 0; u < 16; ++u) {
            float vn = rvn[u * kF];
            float vo = rvo[u * kF];
            float t1 = (vn - vo) * kInvW;
            mean += t1;
            qss   = __fmaf_rn(t1, vn + vo, qss);
            float var = __fmaf_rn(-mean, mean, qss);
            __stcs(po2 + u * kF, (vn - mean) * rsqrtf(var));
        }
        vnF += 16 * kF; if (vnF == kRLf) vnF = 0;
        po2 += 16 * kF;
        issue16();
    }
}

extern "C" void kernel_launch(void* const* d_in, const int* in_sizes, int n_in,
                              void* d_out, int out_size)
{
    const float* x = (const float*)d_in[0];
    float* o = (float*)d_out;
    (void)in_sizes; (void)n_in; (void)out_size;

    cudaFuncSetAttribute(cmn_kernel,
                         cudaFuncAttributeMaxDynamicSharedMemorySize, (int)kSmemB);
    cmn_kernel<<<kGrid, kF, kSmemB>>>(x, o);
}

// round 17
// speedup vs baseline: 1.0658x; 1.0658x over previous
#include <cuda_runtime.h>
#include <cstdint>

// SlidingWindowCmn (16, 60000, 80) fp32, window=600, min=100, center=False,
// norm_vars=True.
// R6 (best: 127.2us) with ISSUE-BEFORE-CONSUME: in each 16-row group the
// next cp.async fill is issued right after wait_group+__syncthreads, ahead
// of the LDS/FMA body, so fills get ~400 extra cycles of slack and the
// wait is never exposed. Safety: issuing group g+5 overwrites slot-rows
// base-624..-609; body reads span base-601..base+15; in-flight fills write
// base-688..-609 -- all disjoint. Ring 704 rows (+8 mirror), lead 5.

namespace {
constexpr int kB      = 16;
constexpr int kT      = 60000;
constexpr int kF      = 80;
constexpr int kWin    = 600;
constexpr int kMin    = 100;
constexpr int kChunks = 9;
constexpr int kL      = 6672;               // 8*6672 + 6624 = 60000
constexpr int kRL     = 704;                // logical ring rows
constexpr int kRLf    = kRL * kF;           // 56320 floats
constexpr uint32_t kRLb = kRL * 320u;       // 225280 bytes (logical)
constexpr uint32_t kSmemB = (kRL + 8) * 320u;   // 227840 bytes (+8 mirror)
constexpr int kVOf    = (kRL - kWin - 1) * kF;  // 103 rows -> 8240 floats
constexpr float kInvW = 1.0f / 601.0f;
constexpr int kGrid   = kB * kChunks;       // 144
}

__device__ __forceinline__ uint32_t smem_u32(const void* p) {
    uint32_t a;
    asm("{ .reg .u64 t; cvta.to.shared.u64 t, %1; cvt.u32.u64 %0, t; }"
        : "=r"(a) : "l"(p));
    return a;
}
__device__ __forceinline__ void cpa16(uint32_t s, const float* g) {
    asm volatile("cp.async.cg.shared.global [%0], [%1], 16;" :: "r"(s), "l"(g));
}
__device__ __forceinline__ void cpcommit() {
    asm volatile("cp.async.commit_group;" ::: "memory");
}
__device__ __forceinline__ void cpwait4() {
    asm volatile("cp.async.wait_group 4;" ::: "memory");
}

__global__ void __launch_bounds__(kF, 1)
cmn_kernel(const float* __restrict__ x, float* __restrict__ out)
{
    extern __shared__ float ring[];
    const int f = threadIdx.x;                    // feature 0..79
    const int c = blockIdx.x % kChunks;
    const int b = blockIdx.x / kChunks;

    const float* xb = x + (size_t)b * kT * kF;
    const int start = c * kL;
    const int end   = (c == kChunks - 1) ? kT : start + kL;

    const uint32_t rsb = smem_u32(ring);
    const float* pClamp = x + ((size_t)kB * kT - 16) * kF;  // last full group

    int vnF;                  // consume group float-offset (slot*80)
    uint32_t issB;            // issue group byte-offset
    const float* pIss;
    if (c == 0) {
        vnF = 0; issB = 0; pIss = xb;
    } else {
        const int t0   = start - 608;             // 16-aligned; 7 pad + 601 warmup
        const int slot = t0 % kRL;                // multiple of 16
        vnF = slot * kF; issB = (uint32_t)slot * 320u;
        pIss = xb + (size_t)t0 * kF;
    }

    auto issue16 = [&]() {
        const float* q  = (pIss > pClamp) ? pClamp : pIss;
        const float* qt = q + f * 4;                         // 16B per thread
        const uint32_t a = rsb + issB + (uint32_t)(f << 4);
        cpa16(a,         qt);
        cpa16(a + 1280u, qt + 320);
        cpa16(a + 2560u, qt + 640);
        cpa16(a + 3840u, qt + 960);
        if (issB == 0) {                          // wrap group: mirror rows 0..7
            const uint32_t m = rsb + kRLb + (uint32_t)(f << 4);
            cpa16(m,         qt);
            cpa16(m + 1280u, qt + 320);
        }
        cpcommit();
        pIss += 16 * kF;
        issB += 5120u; if (issB == kRLb) issB = 0;
    };

    // prologue: 5 groups (80 rows) in flight
    #pragma unroll 1
    for (int g = 0; g < 5; ++g) issue16();

    float s = 0.f, ss = 0.f, mean = 0.f, qss = 0.f;
    float* po = out + (size_t)b * kT * kF + f;
    int nSteady;

    if (c == 0) {
        // groups 0..5: rows 0..95 accumulate
        #pragma unroll 1
        for (int g = 0; g < 6; ++g) {
            cpwait4(); __syncthreads();
            issue16();                             // fill ahead of body
            const float* rv = ring + vnF + f;
            #pragma unroll
            for (int u = 0; u < 16; ++u) {
                float v = rv[u * kF]; s += v; ss = __fmaf_rn(v, v, ss);
            }
            vnF += 16 * kF;
        }
        // group 6: rows 96..111
        {
            cpwait4(); __syncthreads();
            issue16();
            const float* rv = ring + vnF + f;
            #pragma unroll
            for (int u = 0; u < 4; ++u) {          // rows 96..99
                float v = rv[u * kF]; s += v; ss = __fmaf_rn(v, v, ss);
            }
            const float inv = 1.0f / (float)kMin;  // burst rows 0..99
            const float m0  = s * inv;
            const float vr0 = __fmaf_rn(-m0, m0, ss * inv);
            const float rs0 = rsqrtf(vr0);
            #pragma unroll 4
            for (int t = 0; t < kMin; ++t) {
                float v = ring[t * kF + f];
                __stcs(po + t * kF, (v - m0) * rs0);
            }
            float n = 100.0f;
            #pragma unroll
            for (int u = 4; u < 16; ++u) {         // rows 100..111 growing
                float v = rv[u * kF]; s += v; ss = __fmaf_rn(v, v, ss);
                n += 1.0f;
                float inv2 = __fdividef(1.0f, n);
                float m    = s * inv2;
                float var  = __fmaf_rn(-m, m, ss * inv2);
                __stcs(po + (96 + u) * kF, (v - m) * rsqrtf(var));
            }
            vnF += 16 * kF;
        }
        // groups 7..36: rows 112..591 growing
        po += 112 * kF;
        float n = 112.0f;
        #pragma unroll 1
        for (int g = 7; g < 37; ++g) {
            cpwait4(); __syncthreads();
            issue16();
            const float* rv = ring + vnF + f;
            #pragma unroll
            for (int u = 0; u < 16; ++u) {
                float v = rv[u * kF]; s += v; ss = __fmaf_rn(v, v, ss);
                n += 1.0f;
                float inv = __fdividef(1.0f, n);
                float m   = s * inv;
                float var = __fmaf_rn(-m, m, ss * inv);
                __stcs(po + u * kF, (v - m) * rsqrtf(var));
            }
            vnF += 16 * kF; po += 16 * kF;
        }
        // group 37: rows 592..607 (transition at t=600)
        {
            cpwait4(); __syncthreads();
            issue16();
            const float* rv = ring + vnF + f;
            #pragma unroll
            for (int u = 0; u < 8; ++u) {          // rows 592..599 growing
                float v = rv[u * kF]; s += v; ss = __fmaf_rn(v, v, ss);
                n += 1.0f;
                float inv = __fdividef(1.0f, n);
                float m   = s * inv;
                float var = __fmaf_rn(-m, m, ss * inv);
                __stcs(po + u * kF, (v - m) * rsqrtf(var));
            }
            mean = s * kInvW; qss = ss * kInvW;
            #pragma unroll
            for (int u = 8; u < 16; ++u) {         // rows 600..607 steady-1
                float vn = rv[u * kF];
                float vo = (u == 8) ? 0.0f : ring[(u - 9) * kF + f];
                float t1 = (vn - vo) * kInvW;
                mean += t1;
                qss   = __fmaf_rn(t1, vn + vo, qss);
                float var = __fmaf_rn(-mean, mean, qss);
                __stcs(po + u * kF, (vn - mean) * rsqrtf(var));
            }
            vnF += 16 * kF;                        // vnF = 608*kF
        }
        nSteady = (kL - 608) / 16;                 // 379
    } else {
        // warmup group 0: rows t0+7 .. t0+15 (start-601 .. start-593)
        {
            cpwait4(); __syncthreads();
            issue16();
            const float* rv = ring + vnF + f;
            #pragma unroll
            for (int u = 7; u < 16; ++u) {
                float v = rv[u * kF]; s += v; ss = __fmaf_rn(v, v, ss);
            }
            vnF += 16 * kF; if (vnF == kRLf) vnF = 0;
        }
        // warmup groups 1..37: 592 rows
        #pragma unroll 1
        for (int g = 1; g < 38; ++g) {
            cpwait4(); __syncthreads();
            issue16();
            const float* rv = ring + vnF + f;
            #pragma unroll
            for (int u = 0; u < 16; ++u) {
                float v = rv[u * kF]; s += v; ss = __fmaf_rn(v, v, ss);
            }
            vnF += 16 * kF; if (vnF == kRLf) vnF = 0;
        }
        mean = s * kInvW; qss = ss * kInvW;
        nSteady = (end - start) / 16;              // 417 or 414
    }

    // ---- steady sliding loop ----
    const int g0row = (c == 0) ? 608 : start;
    float* po2 = out + (size_t)b * kT * kF + (size_t)g0row * kF + f;
    #pragma unroll 1
    for (int g = 0; g < nSteady; ++g) {
        cpwait4(); __syncthreads();
        issue16();                                 // fill ahead of body
        const float* rvn = ring + vnF + f;
        int voF = vnF + kVOf;                      // slot (t-601), group-aligned
        if (voF >= kRLf) voF -= kRLf;              // one wrap check / 16 rows
        const float* rvo = ring + voF + f;         // mirror covers straddle
        #pragma unroll
        for (int u = 0; u < 16; ++u) {
            float vn = rvn[u * kF];
            float vo = rvo[u * kF];
            float t1 = (vn - vo) * kInvW;
            mean += t1;
            qss   = __fmaf_rn(t1, vn + vo, qss);
            float var = __fmaf_rn(-mean, mean, qss);
            __stcs(po2 + u * kF, (vn - mean) * rsqrtf(var));
        }
        vnF += 16 * kF; if (vnF == kRLf) vnF = 0;
        po2 += 16 * kF;
    }
}

extern "C" void kernel_launch(void* const* d_in, const int* in_sizes, int n_in,
                              void* d_out, int out_size)
{
    const float* x = (const float*)d_in[0];
    float* o = (float*)d_out;
    (void)in_sizes; (void)n_in; (void)out_size;

    cudaFuncSetAttribute(cmn_kernel,
                         cudaFuncAttributeMaxDynamicSharedMemorySize, (int)kSmemB);
    cmn_kernel<<<kGrid, kF, kSmemB>>>(x, o);
}